// round 2
// baseline (speedup 1.0000x reference)
#include <cuda_runtime.h>
#include <cuda_bf16.h>

// RandomResizedCrop resample: out[i] = lerp over cropped audio at idx = f32(i)*delta,
// delta = f32(crop_len-1)/f32(n-1). Interp math is expression-identical to the
// passing R1 kernel (bit-matches it); this version stages each block's input
// window in shared memory to take the 2x gather off the L1 global path.
//
// delta < 1 (scale in (0.8,1.0)), so 2048 consecutive outputs need a contiguous
// input span of <= 2048*delta + fp32-rounding slack (+-2) floats.

#define THREADS      256
#define OUT_PER_THR  8
#define OUT_TILE     (THREADS * OUT_PER_THR)   // 2048 outputs per block
#define SMEM_FLOATS  2080                      // covers 2047*delta + 9 + align slack
#define SMEM_VEC4    (SMEM_FLOATS / 4)         // 520

__global__ __launch_bounds__(THREADS)
void resample_smem_kernel(const float* __restrict__ audio,
                          const int* __restrict__ p_crop,
                          const int* __restrict__ p_start,
                          float* __restrict__ out,
                          int n, int audio_len) {
    __shared__ float s[SMEM_FLOATS];

    const int crop_len = __ldg(p_crop);
    const int start    = __ldg(p_start);
    const float delta  = (float)(crop_len - 1) / (float)(n - 1);
    const int hi_clamp = crop_len - 1;

    const int o0 = blockIdx.x * OUT_TILE;

    // Input window start (uniform across block). floor(o0*delta) is within +-1
    // of the true value (o0 exact in fp32: multiple of 2048); per-i idx deviates
    // by <= 2 more. -4 margin covers it; then round down for float4 alignment
    // of (audio + start + S).
    int S = (int)floorf((float)o0 * delta) - 4;
    if (S < 0) S = 0;
    S -= ((start + S) & 3);          // keep start+S multiple of 4 (stays >= -3, g >= 0)

    // Cooperative coalesced fill: 520 float4 = 2080 floats.
    #pragma unroll
    for (int j = threadIdx.x; j < SMEM_VEC4; j += THREADS) {
        const int g = start + S + 4 * j;     // >= 0 by construction
        float4 v;
        if (g + 3 < audio_len) {
            v = *reinterpret_cast<const float4*>(audio + g);
        } else {                              // degenerate tail guard (never hot)
            v.x = audio[min(g,     audio_len - 1)];
            v.y = audio[min(g + 1, audio_len - 1)];
            v.z = audio[min(g + 2, audio_len - 1)];
            v.w = audio[min(g + 3, audio_len - 1)];
        }
        *reinterpret_cast<float4*>(s + 4 * j) = v;
    }
    __syncthreads();

    const int i0 = o0 + threadIdx.x * OUT_PER_THR;

    float r[OUT_PER_THR];
    #pragma unroll
    for (int k = 0; k < OUT_PER_THR; k++) {
        int i      = i0 + k;
        float fi   = (float)i;         // RN convert (matches f32 iota rounding)
        float idx  = fi * delta;       // RN multiply (matches XLA linspace)
        int lo     = (int)floorf(idx);
        int hi     = min(lo + 1, hi_clamp);
        float w    = idx - (float)lo;
        float a    = s[lo - S];        // conflict-free: lane stride 7 banks
        float b    = s[hi - S];
        r[k] = (1.0f - w) * a + w * b; // same expression as R1 -> same rounding
    }

    // i0 is 8-aligned, n = 2^25 -> aligned float4 stores
    *reinterpret_cast<float4*>(out + i0)     = make_float4(r[0], r[1], r[2], r[3]);
    *reinterpret_cast<float4*>(out + i0 + 4) = make_float4(r[4], r[5], r[6], r[7]);
}

extern "C" void kernel_launch(void* const* d_in, const int* in_sizes, int n_in,
                              void* d_out, int out_size) {
    const float* audio   = (const float*)d_in[0];
    const int*   p_crop  = (const int*)d_in[1];
    const int*   p_start = (const int*)d_in[2];
    float*       out     = (float*)d_out;

    const int n         = out_size;      // 2^25
    const int audio_len = in_sizes[0];
    const int blocks    = (n + OUT_TILE - 1) / OUT_TILE;   // 16384

    resample_smem_kernel<<<blocks, THREADS>>>(audio, p_crop, p_start, out, n, audio_len);
}

// round 3
// speedup vs baseline: 1.0971x; 1.0971x over previous
#include <cuda_runtime.h>
#include <cuda_bf16.h>

// RandomResizedCrop resample: out[i] = lerp over cropped audio at
// idx = f32(i) * delta, delta = f32(crop_len-1)/f32(n-1) (= 0.875f here).
// Interp math is expression-identical to the passing R1 kernel.
//
// Lane-consecutive mapping: within each gather LDG, adjacent lanes read
// adjacent-ish input addresses (stride 0.875 floats), so a warp's gather
// touches ~1-2 cache lines instead of 4 -> ~3.5x less L1 sector traffic
// than the R1 layout. 8 outputs/thread, all loads issued up front (MLP~16).

#define THREADS      256
#define OUT_PER_THR  8
#define OUT_TILE     (THREADS * OUT_PER_THR)   // 2048

__global__ __launch_bounds__(THREADS)
void resample_lane_kernel(const float* __restrict__ audio,
                          const int* __restrict__ p_crop,
                          const int* __restrict__ p_start,
                          float* __restrict__ out,
                          int n) {
    const int crop_len = __ldg(p_crop);
    const int start    = __ldg(p_start);
    const float delta  = (float)(crop_len - 1) / (float)(n - 1);
    const int hi_clamp = crop_len - 1;
    const float* __restrict__ base = audio + start;

    const int i0 = blockIdx.x * OUT_TILE + threadIdx.x;

    // Phase 1: compute indices/weights and issue ALL gathers (independent).
    float a[OUT_PER_THR], b[OUT_PER_THR], w[OUT_PER_THR];
    #pragma unroll
    for (int k = 0; k < OUT_PER_THR; k++) {
        int i      = i0 + k * THREADS;
        float fi   = (float)i;          // RN convert (matches f32 iota rounding)
        float idx  = fi * delta;        // RN multiply (matches XLA linspace)
        int lo     = (int)floorf(idx);
        int hi     = min(lo + 1, hi_clamp);
        w[k]       = idx - (float)lo;
        a[k]       = __ldg(base + lo);
        b[k]       = __ldg(base + hi);
    }

    // Phase 2: interpolate and store (coalesced STG.32 per instruction).
    #pragma unroll
    for (int k = 0; k < OUT_PER_THR; k++) {
        out[i0 + k * THREADS] = (1.0f - w[k]) * a[k] + w[k] * b[k];
    }
}

extern "C" void kernel_launch(void* const* d_in, const int* in_sizes, int n_in,
                              void* d_out, int out_size) {
    const float* audio   = (const float*)d_in[0];
    const int*   p_crop  = (const int*)d_in[1];
    const int*   p_start = (const int*)d_in[2];
    float*       out     = (float*)d_out;

    const int n      = out_size;                 // 2^25 (multiple of OUT_TILE)
    const int blocks = (n + OUT_TILE - 1) / OUT_TILE;

    resample_lane_kernel<<<blocks, THREADS>>>(audio, p_crop, p_start, out, n);
}